// round 11
// baseline (speedup 1.0000x reference)
#include <cuda_runtime.h>
#include <cstdint>

// Problem constants
#define S_    8
#define U_    8
#define K_    12
#define NEG_  17
#define ZD    64
#define CD    256
#define T_    1140
#define LEN   1128
#define SU    64
#define TOTPOS 72192

#define NCTA 144
#define TILES_PER_CTA 24        // 144*24 = 3456 = 6 kpairs * 9 ltiles * 64 su

__device__ double g_loss[K_];
__device__ double g_acc[K_];

__global__ void zero_accum() {
    int i = threadIdx.x;
    if (i < K_) { g_loss[i] = 0.0; g_acc[i] = 0.0; }
}

__device__ __forceinline__ void bar0() {
    asm volatile("bar.sync 0;" ::: "memory");
}

// ---------------- smem layout (float offsets) ----------------
#define ASB 132
#define AB_BUF (64 * ASB)             // one stage: As[32][132] + Bs[32][132]
#define OFF_AB 0                      // 2 stages
#define OFF_WC (2 * AB_BUF)
#define WC_BUF (128 * ASB)            // wc tile, double buffered
#define OFF_SL (OFF_WC + 2 * WC_BUF)
#define OFF_SA (OFF_SL + 12)
#define SMEM_FLOATS (OFF_SA + 12 + 4)
#define SMEM_BYTES (SMEM_FLOATS * 4)  // ~203 KB -> 1 CTA/SM

// ================= instruction-interleaved fused kernel =================
// Every thread: GEMM chunk of tile i + one loss pair of tile i-1 per segment.
// Uniform control flow; only bar.sync 0. Warp-parity staggers loss vs FFMA
// so each SMSP always has FFMA work while sibling warps wait on gathers.
__global__ __launch_bounds__(256, 1) void fused_il(
    const float* __restrict__ C,
    const float* __restrict__ W,
    const float* __restrict__ Bias,
    const float* __restrict__ z,
    const int* __restrict__ batch_index,
    const int* __restrict__ seq_index)
{
    extern __shared__ float smf[];
    float* sLoss = smf + OFF_SL;
    float* sAcc  = smf + OFF_SA;

    const int tid  = threadIdx.x;
    const int wid  = tid >> 5;
    const int lane = tid & 31;
    const int ty   = tid >> 4;         // GEMM: rows ty*8..+8
    const int tx   = tid & 15;         // GEMM: cols tx*8..+8
    const int g8   = tid >> 3;         // loss: group 0..31
    const int lg   = tid & 7;
    const unsigned gmask = 0xFFu << ((lane >> 3) * 8);

    if (tid < 12) { sLoss[tid] = 0.0f; sAcc[tid] = 0.0f; }
    bar0();

    float lts0 = 0.f, lts1 = 0.f, oks0 = 0.f, oks1 = 0.f;

    for (int i = 0; i <= TILES_PER_CTA; i++) {
        const bool gact = (i < TILES_PER_CTA);
        const bool lact = (i >= 1);

        // ---- current tile (GEMM) indices ----
        int k0 = 0, l0 = 0, su = 0;
        if (gact) {
            const int t  = blockIdx.x * TILES_PER_CTA + i;
            const int kp = t % 6;
            const int rs = t / 6;
            k0 = kp * 2; l0 = (rs % 9) * 128; su = rs / 9;
        }
        // ---- previous tile (loss) indices ----
        int k0p = 0, l0p = 0, sup = 0, sp = 0, up = 0;
        if (lact) {
            const int t  = blockIdx.x * TILES_PER_CTA + (i - 1);
            const int kp = t % 6;
            const int rs = t / 6;
            k0p = kp * 2; l0p = (rs % 9) * 128; sup = rs / 9;
            sp = sup >> 3; up = sup & 7;
        }
        float* wcw = smf + OFF_WC + (i & 1) * WC_BUF;
        const float* wcr = smf + OFF_WC + ((i - 1) & 1) * WC_BUF;

        float acc[8][8];
        if (gact) {
#pragma unroll
            for (int a = 0; a < 8; a++)
#pragma unroll
                for (int b = 0; b < 8; b++) acc[a][b] = 0.0f;
        }

        // ---- preload chunk 0 into stage 0 ----
        if (gact) {
            float* dA = smf + OFF_AB;
            float* dB = dA + 32 * ASB;
#pragma unroll
            for (int r = 0; r < 4; r++) {
                int f = r * 256 + tid;
                int row = f >> 3, c4 = f & 7;
                int rr = l0 + row; if (rr > T_ - 1) rr = T_ - 1;
                float4 v = *(const float4*)(C + ((size_t)su * T_ + rr) * CD + c4 * 4);
                dA[(c4 * 4 + 0) * ASB + row] = v.x;
                dA[(c4 * 4 + 1) * ASB + row] = v.y;
                dA[(c4 * 4 + 2) * ASB + row] = v.z;
                dA[(c4 * 4 + 3) * ASB + row] = v.w;
                const float* brow = W + ((size_t)(k0 + (row >> 6)) * ZD + (row & 63)) * CD;
                float4 w4 = *(const float4*)(brow + c4 * 4);
                dB[(c4 * 4 + 0) * ASB + row] = w4.x;
                dB[(c4 * 4 + 1) * ASB + row] = w4.y;
                dB[(c4 * 4 + 2) * ASB + row] = w4.z;
                dB[(c4 * 4 + 3) * ASB + row] = w4.w;
            }
        }
        bar0();

        for (int r2 = 0; r2 < 8; r2++) {
            // ---- prefetch next chunk to registers (issue early) ----
            float4 aL[4], bL[4];
            const bool pf = gact && (r2 < 7);
            if (pf) {
                const int ktb = (r2 + 1) * 32;
#pragma unroll
                for (int r = 0; r < 4; r++) {
                    int f = r * 256 + tid;
                    int row = f >> 3, c4 = f & 7;
                    int rr = l0 + row; if (rr > T_ - 1) rr = T_ - 1;
                    aL[r] = *(const float4*)(C + ((size_t)su * T_ + rr) * CD + ktb + c4 * 4);
                    const float* brow = W + ((size_t)(k0 + (row >> 6)) * ZD + (row & 63)) * CD;
                    bL[r] = *(const float4*)(brow + ktb + c4 * 4);
                }
            }

            const float* Asb = smf + OFF_AB + (r2 & 1) * AB_BUF;
            const float* Bsb = Asb + 32 * ASB;

            // ---- loss pair for tile i-1 (pair = g8*8 + r2) ----
            // and FFMA chunk; warp parity staggers the order.
#define LOSS_PAIR() do {                                                            \
    if (lact) {                                                                     \
        const int pair = g8 * 8 + r2;                                               \
        const int lrow = pair >> 1;                                                 \
        const int kh   = pair & 1;                                                  \
        const int l    = l0p + lrow;                                                \
        if (l < LEN) {                                                              \
            const int k = k0p + kh;                                                 \
            const int kshift = k + 1;                                               \
            const float* wrow = wcr + lrow * ASB + kh * 64;                         \
            const float4 wa = *(const float4*)(wrow + 4 * lg);                      \
            const float4 wb = *(const float4*)(wrow + 32 + 4 * lg);                 \
            const float* zp = z + ((size_t)(sup * T_ + l + kshift)) * ZD;           \
            float4 za = *(const float4*)(zp + 4 * lg);                              \
            float4 zb = *(const float4*)(zp + 32 + 4 * lg);                         \
            float v = wa.x * za.x + wa.y * za.y + wa.z * za.z + wa.w * za.w         \
                    + wb.x * zb.x + wb.y * zb.y + wb.z * zb.z + wb.w * zb.w;        \
            v += __shfl_xor_sync(gmask, v, 1);                                      \
            v += __shfl_xor_sync(gmask, v, 2);                                      \
            v += __shfl_xor_sync(gmask, v, 4);                                      \
            const float pos = v * 0.125f;                                           \
            const int* bip = batch_index + (k * U_ + up) * NEG_;                    \
            const int* sip = seq_index + ((size_t)((k * S_ + sp) * U_ + up) * NEG_) * LEN + l; \
            int bis[NEG_], sis[NEG_];                                               \
            _Pragma("unroll")                                                       \
            for (int n = 0; n < NEG_; n++) {                                        \
                bis[n] = __ldg(bip + n);                                            \
                sis[n] = __ldg(sip + (size_t)n * LEN);                              \
            }                                                                       \
            float m = pos, ssum = 1.0f, ok = 1.0f;                                  \
            _Pragma("unroll")                                                       \
            for (int n = 0; n < NEG_; n++) {                                        \
                const float* zr = z + ((size_t)((sp * 8 + bis[n]) * T_ + sis[n] + kshift)) * ZD; \
                float4 na = *(const float4*)(zr + 4 * lg);                          \
                float4 nb = *(const float4*)(zr + 32 + 4 * lg);                     \
                float d = wa.x * na.x + wa.y * na.y + wa.z * na.z + wa.w * na.w     \
                        + wb.x * nb.x + wb.y * nb.y + wb.z * nb.z + wb.w * nb.w;    \
                d += __shfl_xor_sync(gmask, d, 1);                                  \
                d += __shfl_xor_sync(gmask, d, 2);                                  \
                d += __shfl_xor_sync(gmask, d, 4);                                  \
                d *= 0.125f;                                                        \
                if (d > pos) ok = 0.0f;                                             \
                if (d > m) { ssum = ssum * __expf(m - d) + 1.0f; m = d; }           \
                else       { ssum += __expf(d - m); }                               \
            }                                                                       \
            float res = m + __logf(ssum) - pos;                                     \
            if (kh) { lts1 += res; oks1 += ok; }                                    \
            else    { lts0 += res; oks0 += ok; }                                    \
        }                                                                           \
    }                                                                               \
} while (0)

#define FFMA_CHUNK() do {                                                           \
    if (gact) {                                                                     \
        _Pragma("unroll 16")                                                        \
        for (int kk = 0; kk < 32; kk++) {                                           \
            float4 a0 = *(const float4*)&Asb[kk * ASB + ty * 8];                    \
            float4 a1 = *(const float4*)&Asb[kk * ASB + ty * 8 + 4];                \
            float4 b0 = *(const float4*)&Bsb[kk * ASB + tx * 8];                    \
            float4 b1 = *(const float4*)&Bsb[kk * ASB + tx * 8 + 4];                \
            float a[8] = {a0.x, a0.y, a0.z, a0.w, a1.x, a1.y, a1.z, a1.w};          \
            float b[8] = {b0.x, b0.y, b0.z, b0.w, b1.x, b1.y, b1.z, b1.w};          \
            _Pragma("unroll")                                                       \
            for (int x = 0; x < 8; x++)                                             \
                _Pragma("unroll")                                                   \
                for (int y = 0; y < 8; y++) acc[x][y] += a[x] * b[y];               \
        }                                                                           \
    }                                                                               \
} while (0)

            if (wid & 1) { FFMA_CHUNK(); LOSS_PAIR(); }
            else         { LOSS_PAIR(); FFMA_CHUNK(); }

            // ---- store prefetched chunk into other stage ----
            if (pf) {
                float* dA = smf + OFF_AB + ((r2 + 1) & 1) * AB_BUF;
                float* dB = dA + 32 * ASB;
#pragma unroll
                for (int r = 0; r < 4; r++) {
                    int f = r * 256 + tid;
                    int row = f >> 3, c4 = f & 7;
                    dA[(c4 * 4 + 0) * ASB + row] = aL[r].x;
                    dA[(c4 * 4 + 1) * ASB + row] = aL[r].y;
                    dA[(c4 * 4 + 2) * ASB + row] = aL[r].z;
                    dA[(c4 * 4 + 3) * ASB + row] = aL[r].w;
                    dB[(c4 * 4 + 0) * ASB + row] = bL[r].x;
                    dB[(c4 * 4 + 1) * ASB + row] = bL[r].y;
                    dB[(c4 * 4 + 2) * ASB + row] = bL[r].z;
                    dB[(c4 * 4 + 3) * ASB + row] = bL[r].w;
                }
            }
            bar0();
        }

        // ---- tile end: write wc (+bias); flush loss of tile i-1 ----
        if (gact) {
            float bias[8];
#pragma unroll
            for (int j = 0; j < 8; j++) {
                int n = tx * 8 + j;
                bias[j] = __ldg(Bias + (k0 + (n >> 6)) * ZD + (n & 63));
            }
#pragma unroll
            for (int x = 0; x < 8; x++) {
                int row = ty * 8 + x;
#pragma unroll
                for (int j = 0; j < 8; j++)
                    wcw[row * ASB + tx * 8 + j] = acc[x][j] + bias[j];
            }
        }
        if (lact) {
            lts0 += __shfl_xor_sync(0xffffffffu, lts0, 8);
            lts0 += __shfl_xor_sync(0xffffffffu, lts0, 16);
            lts1 += __shfl_xor_sync(0xffffffffu, lts1, 8);
            lts1 += __shfl_xor_sync(0xffffffffu, lts1, 16);
            oks0 += __shfl_xor_sync(0xffffffffu, oks0, 8);
            oks0 += __shfl_xor_sync(0xffffffffu, oks0, 16);
            oks1 += __shfl_xor_sync(0xffffffffu, oks1, 8);
            oks1 += __shfl_xor_sync(0xffffffffu, oks1, 16);
            if (lane == 0) {
                atomicAdd(&sLoss[k0p],     lts0);
                atomicAdd(&sLoss[k0p + 1], lts1);
                atomicAdd(&sAcc[k0p],      oks0);
                atomicAdd(&sAcc[k0p + 1],  oks1);
            }
            lts0 = lts1 = oks0 = oks1 = 0.f;
        }
        bar0();
    }

    if (tid < 12) {
        atomicAdd(&g_loss[tid], (double)sLoss[tid]);
        atomicAdd(&g_acc[tid],  (double)sAcc[tid]);
    }
}

// ================= finalize =================
__global__ void finalize(float* __restrict__ out, int out_size) {
    if (threadIdx.x == 0) {
        double tot = 0.0;
#pragma unroll
        for (int kk = 0; kk < K_; kk++) tot += g_loss[kk];
        if (out_size > 0) out[0] = (float)(tot / ((double)K_ * (double)TOTPOS));
#pragma unroll
        for (int kk = 0; kk < K_; kk++)
            if (1 + kk < out_size) out[1 + kk] = (float)(g_acc[kk] / (double)TOTPOS);
    }
}

// ---------------- launch ----------------
extern "C" void kernel_launch(void* const* d_in, const int* in_sizes, int n_in,
                              void* d_out, int out_size) {
    const float* z  = (const float*)d_in[0];
    const float* c  = (const float*)d_in[1];
    const float* W  = (const float*)d_in[2];
    const float* b  = (const float*)d_in[3];
    const int* bidx = (const int*)d_in[4];
    const int* sidx = (const int*)d_in[5];

    cudaFuncSetAttribute(fused_il, cudaFuncAttributeMaxDynamicSharedMemorySize, SMEM_BYTES);

    zero_accum<<<1, 32>>>();

    fused_il<<<NCTA, 256, SMEM_BYTES>>>(c, W, b, z, bidx, sidx);

    finalize<<<1, 32>>>((float*)d_out, out_size);
}